// round 4
// baseline (speedup 1.0000x reference)
#include <cuda_runtime.h>

#define Bb 8
#define Nn 1024
#define Ee 10
#define NCH 32    // j-chunks in colsum
#define JS 4      // j-splits in the iteration matmul
#define JCH 256   // j per split

__device__ float g_Ppart[Bb * NCH * Nn];
__device__ float g_Mpart[Bb * NCH * Nn];
__device__ float g_base[Bb * Nn * Ee];
__device__ float g_h[2][Bb * Ee * Nn];        // ping-pong, transposed [b][e][i]
__device__ float g_part[JS * Bb * Ee * Nn];   // matmul partials [js][b][e][i]
__device__ float g_S[Bb * Ee];
__device__ float g_wp[Ee * Ee];

__device__ __forceinline__ void ffma2(unsigned long long& acc,
                                      unsigned long long a,
                                      unsigned long long b) {
    asm("fma.rn.f32x2 %0, %1, %2, %0;" : "+l"(acc) : "l"(a), "l"(b));
}

// ---------------------------------------------------------------------------
// Kernel A: column sums of max(w,0)/min(w,0) over source nodes j, float4-wide.
// Stages Wp. (No prefetch — it regressed in R3.)
// ---------------------------------------------------------------------------
__global__ void __launch_bounds__(256) colsum_kernel(
    const float4* __restrict__ w4, const float* __restrict__ wp)
{
    int i4 = threadIdx.x;
    int jc = blockIdx.x;
    int b  = blockIdx.y;
    if (jc == 0 && b == 0 && threadIdx.x < Ee * Ee)
        g_wp[threadIdx.x] = wp[threadIdx.x];

    const float4* p = w4 + ((size_t)(b * Nn + jc * 32) * 256) + i4;
    float4 sp = make_float4(0.f, 0.f, 0.f, 0.f);
    float4 sm = make_float4(0.f, 0.f, 0.f, 0.f);
#pragma unroll 8
    for (int j = 0; j < 32; j++) {
        float4 v = p[(size_t)j * 256];
        sp.x += fmaxf(v.x, 0.f); sm.x += fminf(v.x, 0.f);
        sp.y += fmaxf(v.y, 0.f); sm.y += fminf(v.y, 0.f);
        sp.z += fmaxf(v.z, 0.f); sm.z += fminf(v.z, 0.f);
        sp.w += fmaxf(v.w, 0.f); sm.w += fminf(v.w, 0.f);
    }
    ((float4*)g_Ppart)[(b * NCH + jc) * 256 + i4] = sp;
    ((float4*)g_Mpart)[(b * NCH + jc) * 256 + i4] = sm;
}

// ---------------------------------------------------------------------------
// Kernel B: reduce partials, base[b,i,e], emb1 = relu(base), h1 = Wp@emb1.
// Also zeroes g_S.
// ---------------------------------------------------------------------------
__global__ void __launch_bounds__(256) base_kernel(
    const float* __restrict__ feat,
    const float* __restrict__ ws,
    const float* __restrict__ wnb,
    const float* __restrict__ ew)
{
    int idx = blockIdx.x * 256 + threadIdx.x;
    int b = idx >> 10, i = idx & 1023;
    if (idx < Bb * Ee) g_S[idx] = 0.f;

    float P = 0.f, M = 0.f;
#pragma unroll 8
    for (int c = 0; c < NCH; c++) {
        P += g_Ppart[(b * NCH + c) * Nn + i];
        M += g_Mpart[(b * NCH + c) * Nn + i];
    }
    float f = feat[idx];

    float ewv[Ee];
#pragma unroll
    for (int e = 0; e < Ee; e++) ewv[e] = ew[e];

    float emb1[Ee];
#pragma unroll
    for (int e = 0; e < Ee; e++) {
        float cP = 0.f, cM = 0.f;
#pragma unroll
        for (int g = 0; g < Ee; g++) {
            float wv = wnb[e * Ee + g];
            cP += wv * fmaxf(ewv[g], 0.f);
            cM += wv * fminf(ewv[g], 0.f);
        }
        float basev = f * ws[e] + cP * P + cM * M;
        g_base[idx * Ee + e] = basev;
        emb1[e] = fmaxf(basev, 0.f);
    }
#pragma unroll
    for (int e = 0; e < Ee; e++) {
        float hv = 0.f;
#pragma unroll
        for (int g = 0; g < Ee; g++) hv += g_wp[e * Ee + g] * emb1[g];
        g_h[0][(b * Ee + e) * Nn + i] = hv;
    }
}

// ---------------------------------------------------------------------------
// Kernel C1: partial matmul. part[js][b][e][i] = sum_{j in chunk} A[b,i,j]*h[b,j,e]
// grid (Nn/32, JS, Bb) = 1024 CTAs, 256 thr (8 warps x 4 groups x 8 lanes).
// Group = one row; 8 lanes cover 8 consecutive float4 of j. smem = 10 KB.
// f32x2 packed accumulators (10 per lane = 20 regs).
// ---------------------------------------------------------------------------
__global__ void __launch_bounds__(256) mm_kernel(const float* __restrict__ A,
                                                 int src)
{
    __shared__ __align__(16) float sh[Ee * JCH];   // 10 KB
    int js = blockIdx.y;
    int b  = blockIdx.z;
    int tid = threadIdx.x;

    // copy h chunk: sh[e][0..255] = g_h[src][b][e][js*256 .. +256]
    const float4* hsrc = (const float4*)(g_h[src] + (size_t)b * Ee * Nn);
    float4* sh4 = (float4*)sh;
#pragma unroll
    for (int t = tid; t < Ee * 64; t += 256) {
        int e = t >> 6, q = t & 63;
        sh4[t] = hsrc[e * 256 + js * 64 + q];
    }
    __syncthreads();

    int warp = tid >> 5, lane = tid & 31;
    int g = lane >> 3, sub = lane & 7;
    int i = blockIdx.x * 32 + warp * 4 + g;

    const float4* Arow =
        (const float4*)(A + (size_t)(b * Nn + i) * Nn) + js * 64 + sub;
    const float4* shp = (const float4*)sh + sub;

    unsigned long long acc[Ee];
#pragma unroll
    for (int e = 0; e < Ee; e++) acc[e] = 0ull;

#pragma unroll
    for (int k = 0; k < 8; k++) {
        float4 a = Arow[k * 8];
        ulonglong2 a2 = *reinterpret_cast<ulonglong2*>(&a);
#pragma unroll
        for (int e = 0; e < Ee; e++) {
            float4 h4 = shp[e * 64 + k * 8];
            ulonglong2 h2 = *reinterpret_cast<ulonglong2*>(&h4);
            ffma2(acc[e], a2.x, h2.x);
            ffma2(acc[e], a2.y, h2.y);
        }
    }

    // fold halves + 3-level butterfly within the 8-lane group
    float red[Ee];
#pragma unroll
    for (int e = 0; e < Ee; e++) {
        float2 p = *reinterpret_cast<float2*>(&acc[e]);
        float v = p.x + p.y;
        v += __shfl_xor_sync(0xffffffffu, v, 4);
        v += __shfl_xor_sync(0xffffffffu, v, 2);
        v += __shfl_xor_sync(0xffffffffu, v, 1);
        red[e] = v;
    }

    // every lane of the group holds all sums; spread the 10 writes
    float* pp = g_part + ((size_t)(js * Bb + b) * Ee) * Nn + i;
    pp[(size_t)sub * Nn] = red[sub];
    if (sub < Ee - 8) pp[(size_t)(sub + 8) * Nn] = red[sub + 8];
}

// ---------------------------------------------------------------------------
// Kernel C2: epilogue. emb = relu(base + sum_js part); h_out = Wp @ emb.
// Last iter also writes emb_out and accumulates per-batch sums g_S.
// grid 32 x 256 (one thread per row; each CTA within a single batch).
// ---------------------------------------------------------------------------
__global__ void __launch_bounds__(256) epi_kernel(float* __restrict__ emb_out,
                                                  int src, int last)
{
    __shared__ float wps[Ee * Ee];
    __shared__ float sacc[Ee];
    int idx = blockIdx.x * 256 + threadIdx.x;
    int b = idx >> 10, i = idx & 1023;
    if (threadIdx.x < Ee * Ee) wps[threadIdx.x] = g_wp[threadIdx.x];
    if (threadIdx.x < Ee) sacc[threadIdx.x] = 0.f;
    __syncthreads();

    float embf[Ee];
#pragma unroll
    for (int e = 0; e < Ee; e++) {
        float v = g_base[(size_t)idx * Ee + e];
#pragma unroll
        for (int js = 0; js < JS; js++)
            v += g_part[((size_t)(js * Bb + b) * Ee + e) * Nn + i];
        embf[e] = fmaxf(v, 0.f);
    }

    float* hout = g_h[src ^ 1] + (size_t)b * Ee * Nn + i;
#pragma unroll
    for (int e = 0; e < Ee; e++) {
        float hv = 0.f;
#pragma unroll
        for (int f = 0; f < Ee; f++) hv = fmaf(wps[e * Ee + f], embf[f], hv);
        hout[(size_t)e * Nn] = hv;
    }

    if (last) {
        float ssum[Ee];
#pragma unroll
        for (int e = 0; e < Ee; e++) {
            emb_out[(size_t)idx * Ee + e] = embf[e];
            ssum[e] = embf[e];
        }
        // warp-reduce each e, then one atomic per warp per e into smem
#pragma unroll
        for (int e = 0; e < Ee; e++) {
            float v = ssum[e];
            v += __shfl_xor_sync(0xffffffffu, v, 16);
            v += __shfl_xor_sync(0xffffffffu, v, 8);
            v += __shfl_xor_sync(0xffffffffu, v, 4);
            v += __shfl_xor_sync(0xffffffffu, v, 2);
            v += __shfl_xor_sync(0xffffffffu, v, 1);
            if ((threadIdx.x & 31) == 0) atomicAdd(&sacc[e], v);
        }
        __syncthreads();
        if (threadIdx.x < Ee) atomicAdd(&g_S[b * Ee + threadIdx.x], sacc[threadIdx.x]);
    }
}

// ---------------------------------------------------------------------------
// Kernel D: q[b,i] = c_b + sum_e d_e * emb[b,i,e]
// ---------------------------------------------------------------------------
__global__ void __launch_bounds__(256) final_kernel(
    const float* __restrict__ emb,
    float* __restrict__ q,
    const float* __restrict__ wqr,
    const float* __restrict__ wall,
    const float* __restrict__ wact)
{
    int idx = blockIdx.x * 256 + threadIdx.x;
    int b = idx >> 10;
    float cb = 0.f;
#pragma unroll
    for (int f = 0; f < Ee; f++) {
        float t = 0.f;
#pragma unroll
        for (int e = 0; e < Ee; e++) t += wall[f * Ee + e] * g_S[b * Ee + e];
        cb += wqr[f] * t;
    }
    float qv = cb;
#pragma unroll
    for (int e = 0; e < Ee; e++) {
        float t = 0.f;
#pragma unroll
        for (int f = 0; f < Ee; f++) t += wqr[Ee + f] * wact[f * Ee + e];
        qv += t * emb[(size_t)idx * Ee + e];
    }
    q[idx] = qv;
}

extern "C" void kernel_launch(void* const* d_in, const int* in_sizes, int n_in,
                              void* d_out, int out_size) {
    const float* features       = (const float*)d_in[0];
    const float* weights        = (const float*)d_in[1];
    const float* adjacency      = (const float*)d_in[2];
    const float* w_selected     = (const float*)d_in[3];
    const float* w_nbpriors     = (const float*)d_in[4];
    const float* w_nbweights    = (const float*)d_in[5];
    const float* w_nbweights_ew = (const float*)d_in[6];
    const float* w_q_reduc      = (const float*)d_in[7];
    const float* w_q_allembed   = (const float*)d_in[8];
    const float* w_q_action     = (const float*)d_in[9];

    float* out = (float*)d_out;
    float* q = out;                  // [B,N]
    float* emb_out = out + Bb * Nn;  // [B,N,E]

    colsum_kernel<<<dim3(NCH, Bb), 256>>>((const float4*)weights, w_nbpriors);
    base_kernel<<<32, 256>>>(features, w_selected, w_nbweights, w_nbweights_ew);

    dim3 mg(Nn / 32, JS, Bb);   // 1024 CTAs
    // iter 2
    mm_kernel<<<mg, 256>>>(adjacency, 0);
    epi_kernel<<<32, 256>>>(emb_out, 0, 0);
    // iter 3
    mm_kernel<<<mg, 256>>>(adjacency, 1);
    epi_kernel<<<32, 256>>>(emb_out, 1, 0);
    // iter 4
    mm_kernel<<<mg, 256>>>(adjacency, 0);
    epi_kernel<<<32, 256>>>(emb_out, 0, 0);
    // iter 5 (last)
    mm_kernel<<<mg, 256>>>(adjacency, 1);
    epi_kernel<<<32, 256>>>(emb_out, 1, 1);

    final_kernel<<<32, 256>>>(emb_out, q, w_q_reduc, w_q_allembed, w_q_action);
}